// round 1
// baseline (speedup 1.0000x reference)
#include <cuda_runtime.h>
#include <cuda_bf16.h>
#include <cstdint>

// ST-BIF neuron, T=16 sequential recurrence over independent spatial sites.
// x: [T, B, C, H, W] fp32, bias: [C] fp32, out: [T, B, C, H, W] fp32 in {-1,0,1}.
// One thread handles 4 consecutive W-elements (same channel) across all T.

static constexpr int T_STEPS = 16;
static constexpr int B_DIM  = 16;
static constexpr int C_DIM  = 128;
static constexpr int H_DIM  = 32;
static constexpr int W_DIM  = 32;
static constexpr int HW     = H_DIM * W_DIM;                 // 1024
static constexpr int N_ELEM = B_DIM * C_DIM * HW;            // 2,097,152 per timestep
static constexpr int N4     = N_ELEM / 4;                    // 524,288 float4 per timestep
static constexpr int HW4    = HW / 4;                        // 256

static constexpr float TWO_N      = 8.0f;   // threshold 2^3
static constexpr float Q_INIT     = 4.0f;   // 2^2
static constexpr float POS_MAX    = 7.0f;
static constexpr float NEG_MIN    = -8.0f;
static constexpr float BIAS_SCALE = 8.0f / 5.0f;  // 2^N / BIAS_STEPS
static constexpr int   BIAS_STEPS = 5;

__device__ __forceinline__ void stbif_step(float& q, float& acc, float inj, float xin, float& o) {
    // Match reference FP order: q = (q + bias) + x
    q = q + inj;
    q = q + xin;
    // acc is always integral; round() is a no-op.
    bool spike = (q - TWO_N >= 0.0f) && (acc < POS_MAX);
    bool neg   = (q < 0.0f)          && (acc > NEG_MIN);
    float cur  = spike ? 1.0f : (neg ? -1.0f : 0.0f);
    acc += cur;
    q   -= TWO_N * cur;   // spike: -8, neg: +8, none: 0
    o = cur;
}

__global__ __launch_bounds__(256)
void stbif_kernel(const float4* __restrict__ x,
                  const float*  __restrict__ bias,
                  float4*       __restrict__ out) {
    const int tid = blockIdx.x * blockDim.x + threadIdx.x;   // 0 .. N4-1 (exact grid)
    // channel for this float4 (all 4 lanes share c since HW % 4 == 0)
    const int c = (tid / HW4) & (C_DIM - 1);
    const float b4 = __ldg(&bias[c]) * BIAS_SCALE;

    float q0 = Q_INIT, q1 = Q_INIT, q2 = Q_INIT, q3 = Q_INIT;
    float a0 = 0.0f,  a1 = 0.0f,  a2 = 0.0f,  a3 = 0.0f;

    #pragma unroll
    for (int t = 0; t < T_STEPS; t++) {
        const float4 xv = __ldg(&x[(size_t)t * N4 + tid]);
        const float inj = (t < BIAS_STEPS) ? b4 : 0.0f;
        float4 ov;
        stbif_step(q0, a0, inj, xv.x, ov.x);
        stbif_step(q1, a1, inj, xv.y, ov.y);
        stbif_step(q2, a2, inj, xv.z, ov.z);
        stbif_step(q3, a3, inj, xv.w, ov.w);
        out[(size_t)t * N4 + tid] = ov;
    }
}

extern "C" void kernel_launch(void* const* d_in, const int* in_sizes, int n_in,
                              void* d_out, int out_size) {
    const float4* x    = (const float4*)d_in[0];
    const float*  bias = (const float*)d_in[1];
    float4*       out  = (float4*)d_out;

    const int threads = 256;
    const int blocks  = N4 / threads;   // 2048, exact
    stbif_kernel<<<blocks, threads>>>(x, bias, out);
}

// round 2
// speedup vs baseline: 1.0020x; 1.0020x over previous
#include <cuda_runtime.h>
#include <cuda_bf16.h>
#include <cstdint>

// ST-BIF neuron, T=16 sequential recurrence over independent spatial sites.
// Round 2: 2x float4 per thread + software-pipelined prefetch + streaming
// cache hints to raise per-warp MLP and saturate HBM.

static constexpr int T_STEPS = 16;
static constexpr int B_DIM  = 16;
static constexpr int C_DIM  = 128;
static constexpr int H_DIM  = 32;
static constexpr int W_DIM  = 32;
static constexpr int HW     = H_DIM * W_DIM;                 // 1024
static constexpr int N_ELEM = B_DIM * C_DIM * HW;            // 2,097,152 per timestep
static constexpr int N4     = N_ELEM / 4;                    // 524,288 float4 per timestep
static constexpr int HW4    = HW / 4;                        // 256
static constexpr int NPAIR  = N4 / 2;                        // 262,144 threads

static constexpr float TWO_N      = 8.0f;
static constexpr float Q_INIT     = 4.0f;
static constexpr float POS_MAX    = 7.0f;
static constexpr float NEG_MIN    = -8.0f;
static constexpr float BIAS_SCALE = 8.0f / 5.0f;
static constexpr int   BIAS_STEPS = 5;

__device__ __forceinline__ void stbif_step(float& q, float& acc, float inj, float xin, float& o) {
    // Match reference FP order: q = (q + bias) + x
    q = q + inj;
    q = q + xin;
    bool spike = (q - TWO_N >= 0.0f) && (acc < POS_MAX);
    bool neg   = (q < 0.0f)          && (acc > NEG_MIN);
    float cur  = spike ? 1.0f : (neg ? -1.0f : 0.0f);
    acc += cur;
    q   -= TWO_N * cur;
    o = cur;
}

__device__ __forceinline__ float4 ld_stream(const float4* p) {
    return __ldcs(p);
}

__global__ __launch_bounds__(256)
void stbif_kernel2(const float4* __restrict__ x,
                   const float*  __restrict__ bias,
                   float4*       __restrict__ out) {
    const int tid = blockIdx.x * blockDim.x + threadIdx.x;   // 0 .. NPAIR-1 (exact grid)
    const int i0 = tid;               // first site group
    const int i1 = tid + NPAIR;       // second site group (independent chain)

    const int c0 = (i0 / HW4) & (C_DIM - 1);
    const int c1 = (i1 / HW4) & (C_DIM - 1);
    const float b0 = __ldg(&bias[c0]) * BIAS_SCALE;
    const float b1 = __ldg(&bias[c1]) * BIAS_SCALE;

    // State: 8 (q,acc) pairs
    float qa0 = Q_INIT, qa1 = Q_INIT, qa2 = Q_INIT, qa3 = Q_INIT;
    float qb0 = Q_INIT, qb1 = Q_INIT, qb2 = Q_INIT, qb3 = Q_INIT;
    float aa0 = 0.f, aa1 = 0.f, aa2 = 0.f, aa3 = 0.f;
    float ab0 = 0.f, ab1 = 0.f, ab2 = 0.f, ab3 = 0.f;

    // Prologue: prefetch t=0
    float4 xa = ld_stream(&x[i0]);
    float4 xb = ld_stream(&x[i1]);

    #pragma unroll
    for (int t = 0; t < T_STEPS; t++) {
        // Prefetch t+1 before consuming t (compile-time guard, full unroll)
        float4 xa_n, xb_n;
        if (t + 1 < T_STEPS) {
            xa_n = ld_stream(&x[(size_t)(t + 1) * N4 + i0]);
            xb_n = ld_stream(&x[(size_t)(t + 1) * N4 + i1]);
        }

        const float inj0 = (t < BIAS_STEPS) ? b0 : 0.0f;
        const float inj1 = (t < BIAS_STEPS) ? b1 : 0.0f;

        float4 oa, ob;
        stbif_step(qa0, aa0, inj0, xa.x, oa.x);
        stbif_step(qa1, aa1, inj0, xa.y, oa.y);
        stbif_step(qa2, aa2, inj0, xa.z, oa.z);
        stbif_step(qa3, aa3, inj0, xa.w, oa.w);
        stbif_step(qb0, ab0, inj1, xb.x, ob.x);
        stbif_step(qb1, ab1, inj1, xb.y, ob.y);
        stbif_step(qb2, ab2, inj1, xb.z, ob.z);
        stbif_step(qb3, ab3, inj1, xb.w, ob.w);

        __stcs(&out[(size_t)t * N4 + i0], oa);
        __stcs(&out[(size_t)t * N4 + i1], ob);

        if (t + 1 < T_STEPS) { xa = xa_n; xb = xb_n; }
    }
}

extern "C" void kernel_launch(void* const* d_in, const int* in_sizes, int n_in,
                              void* d_out, int out_size) {
    const float4* x    = (const float4*)d_in[0];
    const float*  bias = (const float*)d_in[1];
    float4*       out  = (float4*)d_out;

    const int threads = 256;
    const int blocks  = NPAIR / threads;   // 1024, exact
    stbif_kernel2<<<blocks, threads>>>(x, bias, out);
}